// round 5
// baseline (speedup 1.0000x reference)
#include <cuda_runtime.h>
#include <math.h>

// Problem dims (hardcoded from reference setup_inputs)
#define BD 4
#define CD 16
#define HD 384
#define WD 384
#define HWD (HD*WD)
#define NITER 20

#define C30 0.86602540378443865f

// ---------------- scratch (device globals; no allocation APIs) ----------------
__device__ float2 g_tw[384];                 // W384^t = exp(-2pi i t/384)
__device__ float2 g_T1[BD*CD*HWD];           // k-space scratch (w-index permuted)
__device__ float2 g_c0[BD*HWD];              // constant adjoint-of-data term
__device__ float2 g_Sbar[BD*HWD];            // sum_c conj(coil)
__device__ float2 g_x[BD*HWD];               // FISTA x state
__device__ float2 g_y[BD*HWD];               // FISTA y state
__device__ float  g_PM[BD*HWD];              // permuted mask * (1/384)

// ---------------- complex helpers ----------------
__device__ __forceinline__ float2 cmulf(float2 a, float2 b) {
    return make_float2(a.x*b.x - a.y*b.y, a.x*b.y + a.y*b.x);
}
__device__ __forceinline__ float2 cmul_cs(float2 z, float cr, float ci) {
    return make_float2(z.x*cr - z.y*ci, z.x*ci + z.y*cr);
}
__device__ __forceinline__ int br5(int x) { return (int)(__brev((unsigned)x) >> 27); }
// storage index s (0..383) -> true frequency index
__device__ __forceinline__ int permi(int s) { return (s >> 5) + 12*br5(s & 31); }

__device__ __forceinline__ float2 shfl_xor_c(float2 v, int m) {
    float2 r;
    r.x = __shfl_xor_sync(0xffffffffu, v.x, m);
    r.y = __shfl_xor_sync(0xffffffffu, v.y, m);
    return r;
}

// ---------------- per-lane 12-point DFT (in place) ----------------
__device__ __forceinline__ void dft12(float2* v, float d)
{
    float2 t0[4], t1[4], t2[4];
#pragma unroll
    for (int b = 0; b < 3; b++) {
        float2 A0 = v[b], A1 = v[b+3], A2 = v[b+6], A3 = v[b+9];
        float2 s02 = make_float2(A0.x+A2.x, A0.y+A2.y);
        float2 d02 = make_float2(A0.x-A2.x, A0.y-A2.y);
        float2 s13 = make_float2(A1.x+A3.x, A1.y+A3.y);
        float2 d13 = make_float2(A1.x-A3.x, A1.y-A3.y);
        float2 rot = make_float2(d*d13.y, -d*d13.x);
        float2* t = (b == 0) ? t0 : (b == 1) ? t1 : t2;
        t[0] = make_float2(s02.x+s13.x, s02.y+s13.y);
        t[2] = make_float2(s02.x-s13.x, s02.y-s13.y);
        t[1] = make_float2(d02.x+rot.x, d02.y+rot.y);
        t[3] = make_float2(d02.x-rot.x, d02.y-rot.y);
    }
    const float CR[12] = {1.f,  C30,  .5f, 0.f, -.5f, -C30, -1.f, -C30, -.5f,  0.f,  .5f,  C30};
    const float SI[12] = {0.f,  .5f,  C30, 1.f,  C30,  .5f,  0.f, -.5f, -C30, -1.f, -C30, -.5f};
#pragma unroll
    for (int j = 0; j < 12; j++) {
        int m2 = (2*j) % 12;
        float2 a = (j&3)==0 ? t0[0] : (j&3)==1 ? t0[1] : (j&3)==2 ? t0[2] : t0[3];
        float2 b = (j&3)==0 ? t1[0] : (j&3)==1 ? t1[1] : (j&3)==2 ? t1[2] : t1[3];
        float2 c = (j&3)==0 ? t2[0] : (j&3)==1 ? t2[1] : (j&3)==2 ? t2[2] : t2[3];
        b = cmul_cs(b, CR[j],  -d*SI[j]);
        c = cmul_cs(c, CR[m2], -d*SI[m2]);
        v[j] = make_float2(a.x+b.x+c.x, a.y+b.y+c.y);
    }
}

// ---------------- four-step twiddle: v[j] *= W384^{d*l*j} ----------------
__device__ __forceinline__ void twiddle384(float2* v, int l, float d, const float2* stw)
{
    float2 w1 = stw[l];     w1.y *= d;
    float2 w2 = stw[2*l];   w2.y *= d;
    float2 w3 = stw[3*l];   w3.y *= d;
    float2 w4  = cmulf(w2, w2);
    float2 w5  = cmulf(w2, w3);
    float2 w6  = cmulf(w3, w3);
    float2 w7  = cmulf(w3, w4);
    float2 w8  = cmulf(w4, w4);
    float2 w9  = cmulf(w4, w5);
    float2 w10 = cmulf(w5, w5);
    float2 w11 = cmulf(w5, w6);
    v[1]  = cmulf(v[1],  w1);
    v[2]  = cmulf(v[2],  w2);
    v[3]  = cmulf(v[3],  w3);
    v[4]  = cmulf(v[4],  w4);
    v[5]  = cmulf(v[5],  w5);
    v[6]  = cmulf(v[6],  w6);
    v[7]  = cmulf(v[7],  w7);
    v[8]  = cmulf(v[8],  w8);
    v[9]  = cmulf(v[9],  w9);
    v[10] = cmulf(v[10], w10);
    v[11] = cmulf(v[11], w11);
}

// ---------------- cross-lane 32-pt FFT, radix-2 DIF (natural in -> bitrev out) ----
__device__ __forceinline__ void dif_stages(float2* v, int l, float d, const float2* stw)
{
#pragma unroll
    for (int st = 0; st < 5; st++) {
        const int H = 16 >> st;
        bool up = (l & H) != 0;
        float sgn = up ? -1.f : 1.f;
        float2 w = make_float2(1.f, 0.f);
        if (H > 1) { w = stw[(192/H) * (l & (H-1))]; w.y *= d; }
#pragma unroll
        for (int j = 0; j < 12; j++) {
            float2 p = shfl_xor_c(v[j], H);
            float2 t = make_float2(p.x + sgn*v[j].x, p.y + sgn*v[j].y);
            if (H > 1) v[j] = up ? cmulf(t, w) : t;
            else       v[j] = t;
        }
    }
}

// ---------------- cross-lane 32-pt FFT, radix-2 DIT (bitrev in -> natural out) ----
__device__ __forceinline__ void dit_stages(float2* v, int l, float d, const float2* stw)
{
#pragma unroll
    for (int st = 0; st < 5; st++) {
        const int H = 1 << st;
        bool up = (l & H) != 0;
        float2 w = make_float2(1.f, 0.f);
        if (H > 1) { w = stw[(192/H) * (l & (H-1))]; w.y *= d; }
#pragma unroll
        for (int j = 0; j < 12; j++) {
            float2 p = shfl_xor_c(v[j], H);
            float2 src = up ? v[j] : p;
            float2 t = (H > 1) ? cmulf(w, src) : src;
            v[j] = up ? make_float2(p.x - t.x, p.y - t.y)
                      : make_float2(v[j].x + t.x, v[j].y + t.y);
        }
    }
}

// full 384-pt, natural input -> permuted output; dir=+1 fwd, -1 inv (unnormalized)
__device__ __forceinline__ void fft_dif(float2* v, int l, float d, const float2* stw)
{
    dft12(v, d);
    twiddle384(v, l, d, stw);
    dif_stages(v, l, d, stw);
}
// full 384-pt, permuted input -> natural output
__device__ __forceinline__ void fft_dit(float2* v, int l, float d, const float2* stw)
{
    dit_stages(v, l, d, stw);
    twiddle384(v, l, d, stw);
    dft12(v, d);
}

#define LOAD_STW                                                    \
    __shared__ float2 stw[384];                                     \
    for (int t_ = threadIdx.x; t_ < 384; t_ += blockDim.x) stw[t_] = g_tw[t_];

// ---------------- init ----------------
__global__ void init_tw_kernel()
{
    int t = threadIdx.x;
    if (t < 384) {
        float s, c;
        sincospif(-2.0f * (float)t / 384.0f, &s, &c);
        g_tw[t] = make_float2(c, s);
    }
}

// Sbar = sum_c conj(coil)
__global__ void p1_sbar(const float* __restrict__ csm)
{
    int i = blockIdx.x*blockDim.x + threadIdx.x;
    if (i >= BD*HWD) return;
    int bb = i / HWD, r = i - bb*HWD;
    float sr = 0.f, si = 0.f;
#pragma unroll
    for (int c = 0; c < CD; c++) {
        sr += csm[((bb*2+0)*CD + c)*HWD + r];
        si -= csm[((bb*2+1)*CD + c)*HWD + r];
    }
    g_Sbar[i] = make_float2(sr, si);
}

// permuted mask (both axes) premultiplied by 1/384
__global__ void pmask_kernel(const int* __restrict__ mask)
{
    int i = blockIdx.x*blockDim.x + threadIdx.x;
    if (i >= BD*HWD) return;
    int bb = i / HWD, r = i - bb*HWD;
    int sh = r / WD, sw = r - sh*WD;
    g_PM[i] = (float)mask[bb*HWD + permi(sh)*WD + permi(sw)] * (1.0f/384.0f);
}

// prologue: rows inverse FFT of (mask*b)/384 -> T1 (permuted w storage)
__global__ void __launch_bounds__(256) p2_rows(const float* __restrict__ x0,
                                               const int* __restrict__ mask)
{
    LOAD_STW
    __syncthreads();
    int wid = threadIdx.x >> 5, l = threadIdx.x & 31;
    int task = blockIdx.x*8 + wid;                 // (bb,h)
    int h = task % HD, bb = task / HD;
    const float* bre = x0 + (bb*2+0)*HWD + h*WD;
    const float* bim = x0 + (bb*2+1)*HWD + h*WD;
    const int*   mr  = mask + bb*HWD + h*WD;
    float2 v[12];
#pragma unroll
    for (int k = 0; k < 12; k++) {
        int w = l + 32*k;
        float mv = (float)mr[w] * (1.0f/384.0f);
        v[k] = make_float2(mv*bre[w], mv*bim[w]);
    }
    fft_dif(v, l, -1.f, stw);
    float2* orow = g_T1 + (bb*HD + h)*WD;
#pragma unroll
    for (int j = 0; j < 12; j++) orow[j*32 + l] = v[j];
}

#define KST 388  // float2 stride per column in staging tile

// prologue: cols inverse FFT, * Sbar/384 -> c0 (natural layout, scatter-store)
__global__ void __launch_bounds__(256) p3_cols()
{
    LOAD_STW
    __shared__ float2 tile[8*KST];
    int wid = threadIdx.x >> 5, l = threadIdx.x & 31;
    int wq = blockIdx.x % (WD/8), bb = blockIdx.x / (WD/8);
    int sw0 = wq*8;
    const float2* base = g_T1 + bb*HWD;
#pragma unroll
    for (int i = 0; i < 12; i++) {
        int idx = threadIdx.x + i*256;
        int cc = idx & 7, hh = idx >> 3;
        tile[cc*KST + hh] = base[hh*WD + sw0 + cc];
    }
    __syncthreads();
    float2 v[12];
#pragma unroll
    for (int k = 0; k < 12; k++) v[k] = tile[wid*KST + l + 32*k];
    __syncthreads();
    fft_dif(v, l, -1.f, stw);
#pragma unroll
    for (int j = 0; j < 12; j++) tile[wid*KST + (j + 12*br5(l))] = v[j];
    __syncthreads();
#pragma unroll
    for (int i = 0; i < 12; i++) {
        int idx = threadIdx.x + i*256;
        int cc = idx & 7, hh = idx >> 3;
        int wt = permi(sw0 + cc);
        float2 val = tile[cc*KST + hh];
        val.x *= (1.0f/384.0f); val.y *= (1.0f/384.0f);
        float2 sbv = g_Sbar[bb*HWD + hh*WD + wt];
        g_c0[bb*HWD + hh*WD + wt] = cmulf(sbv, val);
    }
}

// iteration 0 (y = 0): x = y = relu((1-lam)*c0 + lam*zc)
__global__ void k4_first(const float* __restrict__ zk, const float* __restrict__ lam)
{
    int i = blockIdx.x*blockDim.x + threadIdx.x;
    if (i >= BD*HWD) return;
    int bb = i / HWD, r = i - bb*HWD;
    float ll = lam[0];
    float2 c0v = g_c0[i];
    float zr = zk[(bb*2+0)*HWD + r];
    float zi = zk[(bb*2+1)*HWD + r];
    float xr = fmaxf(c0v.x - ll*(c0v.x - zr), 0.f);
    float xi = fmaxf(c0v.y - ll*(c0v.y - zi), 0.f);
    float2 v = make_float2(xr, xi);
    g_x[i] = v;
    g_y[i] = v;
}

// K1 (standalone, first iteration only): rows forward FFT of coil*y -> T1
__global__ void __launch_bounds__(256) k1_rows(const float* __restrict__ csm)
{
    LOAD_STW
    __syncthreads();
    int wid = threadIdx.x >> 5, l = threadIdx.x & 31;
    int task = blockIdx.x*8 + wid;                 // (bb,c,h)
    int h = task % HD;
    int bc = task / HD;
    int c = bc % CD, bb = bc / CD;
    const float*  cre = csm + ((bb*2+0)*CD + c)*HWD + h*WD;
    const float*  cim = csm + ((bb*2+1)*CD + c)*HWD + h*WD;
    const float2* yr  = g_y + (bb*HD + h)*WD;
    float2 v[12];
#pragma unroll
    for (int k = 0; k < 12; k++) {
        int w = l + 32*k;
        float2 yv = yr[w];
        float a = cre[w], b = cim[w];
        v[k] = make_float2(a*yv.x - b*yv.y, a*yv.y + b*yv.x);
    }
    fft_dif(v, l, 1.f, stw);
    float2* orow = g_T1 + ((bb*CD + c)*HD + h)*WD;
#pragma unroll
    for (int j = 0; j < 12; j++) orow[j*32 + l] = v[j];
}

// K2: cols fwd FFT, permuted-mask multiply (with 1/384), cols inverse FFT, in place.
__global__ void __launch_bounds__(256) k2_cols()
{
    LOAD_STW
    __shared__ float2 tile[8*KST];
    int wid = threadIdx.x >> 5, l = threadIdx.x & 31;
    int wq = blockIdx.x % (WD/8);
    int bc = blockIdx.x / (WD/8);
    int c = bc % CD, bb = bc / CD;
    int sw0 = wq*8;
    float2* base = g_T1 + (bb*CD + c)*HWD;
#pragma unroll
    for (int i = 0; i < 12; i++) {
        int idx = threadIdx.x + i*256;
        int cc = idx & 7, hh = idx >> 3;
        tile[cc*KST + hh] = base[hh*WD + sw0 + cc];
    }
    __syncthreads();
    float2 v[12];
#pragma unroll
    for (int k = 0; k < 12; k++) v[k] = tile[wid*KST + l + 32*k];
    __syncthreads();
    // issue PM loads (to regs) so they overlap the forward FFT
    float pmr[12];
    const float* PM = g_PM + bb*HWD;
#pragma unroll
    for (int i = 0; i < 12; i++) {
        int idx = threadIdx.x + i*256;
        int cc = idx & 7, sh = idx >> 3;
        pmr[i] = PM[sh*WD + sw0 + cc];
    }
    fft_dif(v, l, 1.f, stw);
    // stage PM into smem (reuse tile region as float, stride 392)
    float* tf = (float*)tile;
#pragma unroll
    for (int i = 0; i < 12; i++) {
        int idx = threadIdx.x + i*256;
        int cc = idx & 7, sh = idx >> 3;
        tf[cc*392 + sh] = pmr[i];
    }
    __syncthreads();
#pragma unroll
    for (int j = 0; j < 12; j++) {
        float m = tf[wid*392 + j*32 + l];
        v[j].x *= m; v[j].y *= m;
    }
    __syncthreads();          // all PM reads done before tile reuse
    fft_dit(v, l, -1.f, stw);
#pragma unroll
    for (int k = 0; k < 12; k++) tile[wid*KST + l + 32*k] = v[k];
    __syncthreads();
#pragma unroll
    for (int i = 0; i < 12; i++) {
        int idx = threadIdx.x + i*256;
        int cc = idx & 7, hh = idx >> 3;
        base[hh*WD + sw0 + cc] = tile[cc*KST + hh];
    }
}

// K341: fused k3 (row IFFT + conj(coil) reduce) + k4 (FISTA update)
//       + next-iteration k1 (coil*y_new row FFT -> T1, in place).
// One block owns a row-pair (bb, h0, h0+1) across all 16 coils.
__global__ void __launch_bounds__(256) k341(const float* __restrict__ csm,
                                            const float* __restrict__ zk,
                                            const float* __restrict__ lam,
                                            float beta)
{
    LOAD_STW
    __shared__ float2 sred[8*384];     // per-warp partial sums
    __shared__ float2 ynew[2*384];     // updated y rows (natural w)
    int wid = threadIdx.x >> 5, l = threadIdx.x & 31;
    int bb = blockIdx.x / (HD/2);
    int h0 = (blockIdx.x % (HD/2)) * 2;
    __syncthreads();                   // stw visible

    // ---- Phase A: k3 — rows inverse FFT, conj(coil) accumulate (4 coils/warp)
    {
        int r = wid >> 2, q = wid & 3;
        int h = h0 + r;
        float2 acc[12];
#pragma unroll
        for (int k = 0; k < 12; k++) acc[k] = make_float2(0.f, 0.f);
        for (int cc = 0; cc < 4; cc++) {
            int c = q*4 + cc;
            const float2* row = g_T1 + ((bb*CD + c)*HD + h)*WD;
            float2 v[12];
#pragma unroll
            for (int j = 0; j < 12; j++) v[j] = row[j*32 + l];
            fft_dit(v, l, -1.f, stw);
            const float* cre = csm + ((bb*2+0)*CD + c)*HWD + h*WD;
            const float* cim = csm + ((bb*2+1)*CD + c)*HWD + h*WD;
#pragma unroll
            for (int k = 0; k < 12; k++) {
                int w = l + 32*k;
                float a = cre[w], b = cim[w];
                acc[k].x += a*v[k].x + b*v[k].y;       // conj(coil)*v
                acc[k].y += a*v[k].y - b*v[k].x;
            }
        }
#pragma unroll
        for (int k = 0; k < 12; k++) sred[wid*384 + k*32 + l] = acc[k];
    }
    __syncthreads();

    // ---- Phase B: k4 — reduce partials, FISTA update (warps 0,1)
    if (wid < 2) {
        int r = wid, h = h0 + r;
        const float sc = 1.0f/384.0f;
        float ll = lam[0];
        int rowoff = bb*HWD + h*WD;
        const float* zr_p = zk + (bb*2+0)*HWD + h*WD;
        const float* zi_p = zk + (bb*2+1)*HWD + h*WD;
#pragma unroll
        for (int k = 0; k < 12; k++) {
            int w = l + 32*k;
            float Sx = 0.f, Sy = 0.f;
#pragma unroll
            for (int q = 0; q < 4; q++) {
                float2 p = sred[(r*4+q)*384 + k*32 + l];
                Sx += p.x; Sy += p.y;
            }
            Sx *= sc; Sy *= sc;
            float2 yo = g_y[rowoff + w];
            float2 xo = g_x[rowoff + w];
            float2 c0v = g_c0[rowoff + w];
            float xr = yo.x - Sx + c0v.x;
            float xi = yo.y - Sy + c0v.y;
            xr = xr - ll*(xr - zr_p[w]);
            xi = xi - ll*(xi - zi_p[w]);
            xr = fmaxf(xr, 0.f);
            xi = fmaxf(xi, 0.f);
            float yr = xr + beta*(xr - xo.x);
            float yi = xi + beta*(xi - xo.y);
            g_x[rowoff + w] = make_float2(xr, xi);
            g_y[rowoff + w] = make_float2(yr, yi);
            ynew[r*384 + w] = make_float2(yr, yi);
        }
    }
    __syncthreads();

    // ---- Phase C: k1 for next iteration — coil * y_new, forward row FFT -> T1
    for (int i = 0; i < 4; i++) {
        int t = wid*4 + i;             // 0..31
        int r = t >> 4, c = t & 15;
        int h = h0 + r;
        const float* cre = csm + ((bb*2+0)*CD + c)*HWD + h*WD;
        const float* cim = csm + ((bb*2+1)*CD + c)*HWD + h*WD;
        float2 v[12];
#pragma unroll
        for (int k = 0; k < 12; k++) {
            int w = l + 32*k;
            float2 yv = ynew[r*384 + w];
            float a = cre[w], b = cim[w];
            v[k] = make_float2(a*yv.x - b*yv.y, a*yv.y + b*yv.x);
        }
        fft_dif(v, l, 1.f, stw);
        float2* orow = g_T1 + ((bb*CD + c)*HD + h)*WD;
#pragma unroll
        for (int j = 0; j < 12; j++) orow[j*32 + l] = v[j];
    }
}

// final output: [B,2,H,W] float
__global__ void k5_out(float* __restrict__ out)
{
    int i = blockIdx.x*blockDim.x + threadIdx.x;
    if (i >= BD*HWD) return;
    int bb = i / HWD, r = i - bb*HWD;
    float2 v = g_x[i];
    out[(bb*2+0)*HWD + r] = v.x;
    out[(bb*2+1)*HWD + r] = v.y;
}

// ---------------- host ----------------
extern "C" void kernel_launch(void* const* d_in, const int* in_sizes, int n_in,
                              void* d_out, int out_size)
{
    const float* zk   = (const float*)d_in[0];   // z_k  [B,2,H,W]
    const float* x0   = (const float*)d_in[1];   // x0   [B,2,H,W]
    const float* csm  = (const float*)d_in[2];   // csm  [B,2,C,H,W]
    const float* lam  = (const float*)d_in[3];   // lam  [1]
    const int*   mask = (const int*)d_in[4];     // mask [B,H,W]
    float* out = (float*)d_out;

    // FISTA t-sequence (host, deterministic)
    float betas[NITER];
    double t = 1.0;
    for (int n = 0; n < NITER; n++) {
        double tn = (1.0 + sqrt(1.0 + 4.0*t*t)) / 2.0;
        betas[n] = (float)((t - 1.0) / tn);
        t = tn;
    }

    const int EW_BLOCKS = (BD*HWD) / 256;        // 2304, exact
    init_tw_kernel<<<1, 384>>>();
    p1_sbar<<<EW_BLOCKS, 256>>>(csm);
    pmask_kernel<<<EW_BLOCKS, 256>>>(mask);
    p2_rows<<<BD*HD/8, 256>>>(x0, mask);         // 192
    p3_cols<<<BD*(WD/8), 256>>>();               // 192
    k4_first<<<EW_BLOCKS, 256>>>(zk, lam);
    k1_rows<<<BD*CD*HD/8, 256>>>(csm);           // 3072 — T1 for iteration 1

    for (int n = 1; n < NITER; n++) {
        k2_cols<<<BD*CD*(WD/8), 256>>>();        // 3072
        k341<<<BD*HD/2, 256>>>(csm, zk, lam, betas[n]);   // 768
    }
    k5_out<<<EW_BLOCKS, 256>>>(out);
}

// round 9
// speedup vs baseline: 1.0754x; 1.0754x over previous
#include <cuda_runtime.h>
#include <math.h>

// Problem dims (hardcoded from reference setup_inputs)
#define BD 4
#define CD 16
#define HD 384
#define WD 384
#define HWD (HD*WD)
#define NITER 20

#define C30 0.86602540378443865f

// ---------------- scratch (device globals; no allocation APIs) ----------------
__device__ float2 g_tw[384];                 // W384^t = exp(-2pi i t/384)
__device__ float2 g_T1[BD*CD*HWD];           // k-space scratch (w-index permuted)
__device__ float2 g_c0[BD*HWD];              // adjoint-of-data term (prologue only)
__device__ float2 g_D[BD*HWD];               // D = (1-lam)*c0 + lam*z
__device__ float2 g_Sbar[BD*HWD];            // sum_c conj(coil) (prologue only)
__device__ float2 g_x[BD*HWD];               // FISTA x state
__device__ float2 g_y[BD*HWD];               // FISTA y state
__device__ unsigned char g_PM8[BD*HWD];      // permuted mask (0/1)
__device__ float2 g_csmc[BD*CD*HWD];         // packed (re,im) fp32 csm

// ---------------- complex helpers ----------------
__device__ __forceinline__ float2 cmulf(float2 a, float2 b) {
    return make_float2(a.x*b.x - a.y*b.y, a.x*b.y + a.y*b.x);
}
__device__ __forceinline__ float2 cmul_cs(float2 z, float cr, float ci) {
    return make_float2(z.x*cr - z.y*ci, z.x*ci + z.y*cr);
}
__device__ __forceinline__ int br5(int x) { return (int)(__brev((unsigned)x) >> 27); }
// storage index s (0..383) -> true frequency index
__device__ __forceinline__ int permi(int s) { return (s >> 5) + 12*br5(s & 31); }

__device__ __forceinline__ float2 shfl_xor_c(float2 v, int m) {
    float2 r;
    r.x = __shfl_xor_sync(0xffffffffu, v.x, m);
    r.y = __shfl_xor_sync(0xffffffffu, v.y, m);
    return r;
}

// ---------------- per-lane 12-point DFT (in place) ----------------
__device__ __forceinline__ void dft12(float2* v, float d)
{
    float2 t0[4], t1[4], t2[4];
#pragma unroll
    for (int b = 0; b < 3; b++) {
        float2 A0 = v[b], A1 = v[b+3], A2 = v[b+6], A3 = v[b+9];
        float2 s02 = make_float2(A0.x+A2.x, A0.y+A2.y);
        float2 d02 = make_float2(A0.x-A2.x, A0.y-A2.y);
        float2 s13 = make_float2(A1.x+A3.x, A1.y+A3.y);
        float2 d13 = make_float2(A1.x-A3.x, A1.y-A3.y);
        float2 rot = make_float2(d*d13.y, -d*d13.x);
        float2* t = (b == 0) ? t0 : (b == 1) ? t1 : t2;
        t[0] = make_float2(s02.x+s13.x, s02.y+s13.y);
        t[2] = make_float2(s02.x-s13.x, s02.y-s13.y);
        t[1] = make_float2(d02.x+rot.x, d02.y+rot.y);
        t[3] = make_float2(d02.x-rot.x, d02.y-rot.y);
    }
    const float CR[12] = {1.f,  C30,  .5f, 0.f, -.5f, -C30, -1.f, -C30, -.5f,  0.f,  .5f,  C30};
    const float SI[12] = {0.f,  .5f,  C30, 1.f,  C30,  .5f,  0.f, -.5f, -C30, -1.f, -C30, -.5f};
#pragma unroll
    for (int j = 0; j < 12; j++) {
        int m2 = (2*j) % 12;
        float2 a = (j&3)==0 ? t0[0] : (j&3)==1 ? t0[1] : (j&3)==2 ? t0[2] : t0[3];
        float2 b = (j&3)==0 ? t1[0] : (j&3)==1 ? t1[1] : (j&3)==2 ? t1[2] : t1[3];
        float2 c = (j&3)==0 ? t2[0] : (j&3)==1 ? t2[1] : (j&3)==2 ? t2[2] : t2[3];
        b = cmul_cs(b, CR[j],  -d*SI[j]);
        c = cmul_cs(c, CR[m2], -d*SI[m2]);
        v[j] = make_float2(a.x+b.x+c.x, a.y+b.y+c.y);
    }
}

// ---------------- four-step twiddle: v[j] *= W384^{d*l*j} ----------------
__device__ __forceinline__ void twiddle384(float2* v, int l, float d, const float2* stw)
{
    float2 w1 = stw[l];     w1.y *= d;
    float2 w2 = stw[2*l];   w2.y *= d;
    float2 w3 = stw[3*l];   w3.y *= d;
    float2 w4  = cmulf(w2, w2);
    float2 w5  = cmulf(w2, w3);
    float2 w6  = cmulf(w3, w3);
    float2 w7  = cmulf(w3, w4);
    float2 w8  = cmulf(w4, w4);
    float2 w9  = cmulf(w4, w5);
    float2 w10 = cmulf(w5, w5);
    float2 w11 = cmulf(w5, w6);
    v[1]  = cmulf(v[1],  w1);
    v[2]  = cmulf(v[2],  w2);
    v[3]  = cmulf(v[3],  w3);
    v[4]  = cmulf(v[4],  w4);
    v[5]  = cmulf(v[5],  w5);
    v[6]  = cmulf(v[6],  w6);
    v[7]  = cmulf(v[7],  w7);
    v[8]  = cmulf(v[8],  w8);
    v[9]  = cmulf(v[9],  w9);
    v[10] = cmulf(v[10], w10);
    v[11] = cmulf(v[11], w11);
}

// ---------------- cross-lane 32-pt FFT, radix-2 DIF (natural in -> bitrev out) ----
__device__ __forceinline__ void dif_stages(float2* v, int l, float d, const float2* stw)
{
#pragma unroll
    for (int st = 0; st < 5; st++) {
        const int H = 16 >> st;
        bool up = (l & H) != 0;
        float sgn = up ? -1.f : 1.f;
        float2 w = make_float2(1.f, 0.f);
        if (H > 1) { w = stw[(192/H) * (l & (H-1))]; w.y *= d; }
#pragma unroll
        for (int j = 0; j < 12; j++) {
            float2 p = shfl_xor_c(v[j], H);
            float2 t = make_float2(p.x + sgn*v[j].x, p.y + sgn*v[j].y);
            if (H > 1) v[j] = up ? cmulf(t, w) : t;
            else       v[j] = t;
        }
    }
}

// ---------------- cross-lane 32-pt FFT, radix-2 DIT (bitrev in -> natural out) ----
__device__ __forceinline__ void dit_stages(float2* v, int l, float d, const float2* stw)
{
#pragma unroll
    for (int st = 0; st < 5; st++) {
        const int H = 1 << st;
        bool up = (l & H) != 0;
        float2 w = make_float2(1.f, 0.f);
        if (H > 1) { w = stw[(192/H) * (l & (H-1))]; w.y *= d; }
#pragma unroll
        for (int j = 0; j < 12; j++) {
            float2 p = shfl_xor_c(v[j], H);
            float2 src = up ? v[j] : p;
            float2 t = (H > 1) ? cmulf(w, src) : src;
            v[j] = up ? make_float2(p.x - t.x, p.y - t.y)
                      : make_float2(v[j].x + t.x, v[j].y + t.y);
        }
    }
}

// full 384-pt, natural input -> permuted output; dir=+1 fwd, -1 inv (unnormalized)
__device__ __forceinline__ void fft_dif(float2* v, int l, float d, const float2* stw)
{
    dft12(v, d);
    twiddle384(v, l, d, stw);
    dif_stages(v, l, d, stw);
}
// full 384-pt, permuted input -> natural output
__device__ __forceinline__ void fft_dit(float2* v, int l, float d, const float2* stw)
{
    dit_stages(v, l, d, stw);
    twiddle384(v, l, d, stw);
    dft12(v, d);
}

#define LOAD_STW                                                    \
    __shared__ float2 stw[384];                                     \
    for (int t_ = threadIdx.x; t_ < 384; t_ += blockDim.x) stw[t_] = g_tw[t_];

// ---------------- init ----------------
__global__ void init_tw_kernel()
{
    int t = threadIdx.x;
    if (t < 384) {
        float s, c;
        sincospif(-2.0f * (float)t / 384.0f, &s, &c);
        g_tw[t] = make_float2(c, s);
    }
}

// Sbar = sum_c conj(coil)  (fp32, prologue only)
__global__ void p1_sbar(const float* __restrict__ csm)
{
    int i = blockIdx.x*blockDim.x + threadIdx.x;
    if (i >= BD*HWD) return;
    int bb = i / HWD, r = i - bb*HWD;
    float sr = 0.f, si = 0.f;
#pragma unroll
    for (int c = 0; c < CD; c++) {
        sr += csm[((bb*2+0)*CD + c)*HWD + r];
        si -= csm[((bb*2+1)*CD + c)*HWD + r];
    }
    g_Sbar[i] = make_float2(sr, si);
}

// pack csm -> float2 (re,im) interleaved
__global__ void prep_csmc(const float* __restrict__ csm)
{
    int i = blockIdx.x*blockDim.x + threadIdx.x;
    if (i >= BD*CD*HWD) return;
    int r = i % HWD;
    int bc = i / HWD;
    int c = bc % CD, bb = bc / CD;
    float re = csm[((bb*2+0)*CD + c)*HWD + r];
    float im = csm[((bb*2+1)*CD + c)*HWD + r];
    g_csmc[i] = make_float2(re, im);
}

// permuted mask (both axes), u8
__global__ void pmask_kernel(const int* __restrict__ mask)
{
    int i = blockIdx.x*blockDim.x + threadIdx.x;
    if (i >= BD*HWD) return;
    int bb = i / HWD, r = i - bb*HWD;
    int sh = r / WD, sw = r - sh*WD;
    g_PM8[i] = (unsigned char)mask[bb*HWD + permi(sh)*WD + permi(sw)];
}

// prologue: rows inverse FFT of (mask*b)/384 -> T1 (permuted w storage)
__global__ void __launch_bounds__(256) p2_rows(const float* __restrict__ x0,
                                               const int* __restrict__ mask)
{
    LOAD_STW
    __syncthreads();
    int wid = threadIdx.x >> 5, l = threadIdx.x & 31;
    int task = blockIdx.x*8 + wid;                 // (bb,h)
    int h = task % HD, bb = task / HD;
    const float* bre = x0 + (bb*2+0)*HWD + h*WD;
    const float* bim = x0 + (bb*2+1)*HWD + h*WD;
    const int*   mr  = mask + bb*HWD + h*WD;
    float2 v[12];
#pragma unroll
    for (int k = 0; k < 12; k++) {
        int w = l + 32*k;
        float mv = (float)mr[w] * (1.0f/384.0f);
        v[k] = make_float2(mv*bre[w], mv*bim[w]);
    }
    fft_dif(v, l, -1.f, stw);
    float2* orow = g_T1 + (bb*HD + h)*WD;
#pragma unroll
    for (int j = 0; j < 12; j++) orow[j*32 + l] = v[j];
}

#define KST 388  // float2 stride per column in staging tile

// prologue: cols inverse FFT, * Sbar/384 -> c0 (natural layout, scatter-store)
__global__ void __launch_bounds__(256) p3_cols()
{
    LOAD_STW
    __shared__ float2 tile[8*KST];
    int wid = threadIdx.x >> 5, l = threadIdx.x & 31;
    int wq = blockIdx.x % (WD/8), bb = blockIdx.x / (WD/8);
    int sw0 = wq*8;
    const float2* base = g_T1 + bb*HWD;
#pragma unroll
    for (int i = 0; i < 12; i++) {
        int idx = threadIdx.x + i*256;
        int cc = idx & 7, hh = idx >> 3;
        tile[cc*KST + hh] = base[hh*WD + sw0 + cc];
    }
    __syncthreads();
    float2 v[12];
#pragma unroll
    for (int k = 0; k < 12; k++) v[k] = tile[wid*KST + l + 32*k];
    __syncthreads();
    fft_dif(v, l, -1.f, stw);
#pragma unroll
    for (int j = 0; j < 12; j++) tile[wid*KST + (j + 12*br5(l))] = v[j];
    __syncthreads();
#pragma unroll
    for (int i = 0; i < 12; i++) {
        int idx = threadIdx.x + i*256;
        int cc = idx & 7, hh = idx >> 3;
        int wt = permi(sw0 + cc);
        float2 val = tile[cc*KST + hh];
        val.x *= (1.0f/384.0f); val.y *= (1.0f/384.0f);
        float2 sbv = g_Sbar[bb*HWD + hh*WD + wt];
        g_c0[bb*HWD + hh*WD + wt] = cmulf(sbv, val);
    }
}

// D = (1-lam)*c0 + lam*z ; iteration 0: x = y = relu(D)
__global__ void kD_init(const float* __restrict__ zk, const float* __restrict__ lam)
{
    int i = blockIdx.x*blockDim.x + threadIdx.x;
    if (i >= BD*HWD) return;
    int bb = i / HWD, r = i - bb*HWD;
    float ll = lam[0];
    float2 c0v = g_c0[i];
    float zr = zk[(bb*2+0)*HWD + r];
    float zi = zk[(bb*2+1)*HWD + r];
    float dr = (1.f - ll)*c0v.x + ll*zr;
    float di = (1.f - ll)*c0v.y + ll*zi;
    g_D[i] = make_float2(dr, di);
    float2 v = make_float2(fmaxf(dr, 0.f), fmaxf(di, 0.f));
    g_x[i] = v;
    g_y[i] = v;
}

// K1: rows forward FFT of coil*y -> T1 (permuted w storage). packed fp32 csm.
__global__ void __launch_bounds__(256) k1_rows()
{
    LOAD_STW
    __syncthreads();
    int wid = threadIdx.x >> 5, l = threadIdx.x & 31;
    int task = blockIdx.x*8 + wid;                 // (bb,c,h)
    int h = task % HD;
    int bc = task / HD;
    int c = bc % CD, bb = bc / CD;
    const float2* ch = g_csmc + (bb*CD + c)*HWD + h*WD;
    const float2* yr = g_y + (bb*HD + h)*WD;
    float2 v[12];
#pragma unroll
    for (int k = 0; k < 12; k++) {
        int w = l + 32*k;
        float2 yv = yr[w];
        float2 cv = ch[w];
        v[k] = make_float2(cv.x*yv.x - cv.y*yv.y, cv.x*yv.y + cv.y*yv.x);
    }
    fft_dif(v, l, 1.f, stw);
    float2* orow = g_T1 + ((bb*CD + c)*HD + h)*WD;
#pragma unroll
    for (int j = 0; j < 12; j++) orow[j*32 + l] = v[j];
}

// K2: cols fwd FFT, permuted-mask multiply (with 1/384), cols inverse FFT, in place.
__global__ void __launch_bounds__(256) k2_cols()
{
    LOAD_STW
    __shared__ float2 tile[8*KST];
    int wid = threadIdx.x >> 5, l = threadIdx.x & 31;
    int wq = blockIdx.x % (WD/8);
    int bc = blockIdx.x / (WD/8);
    int c = bc % CD, bb = bc / CD;
    int sw0 = wq*8;
    float2* base = g_T1 + (bb*CD + c)*HWD;
#pragma unroll
    for (int i = 0; i < 12; i++) {
        int idx = threadIdx.x + i*256;
        int cc = idx & 7, hh = idx >> 3;
        tile[cc*KST + hh] = base[hh*WD + sw0 + cc];
    }
    __syncthreads();
    float2 v[12];
#pragma unroll
    for (int k = 0; k < 12; k++) v[k] = tile[wid*KST + l + 32*k];
    __syncthreads();
    // issue PM loads (to regs) so they overlap the forward FFT
    float pmr[12];
    const unsigned char* PM = g_PM8 + bb*HWD;
#pragma unroll
    for (int i = 0; i < 12; i++) {
        int idx = threadIdx.x + i*256;
        int cc = idx & 7, sh = idx >> 3;
        pmr[i] = (float)PM[sh*WD + sw0 + cc] * (1.0f/384.0f);
    }
    fft_dif(v, l, 1.f, stw);
    // stage PM into smem (reuse tile region as float, stride 392)
    float* tf = (float*)tile;
#pragma unroll
    for (int i = 0; i < 12; i++) {
        int idx = threadIdx.x + i*256;
        int cc = idx & 7, sh = idx >> 3;
        tf[cc*392 + sh] = pmr[i];
    }
    __syncthreads();
#pragma unroll
    for (int j = 0; j < 12; j++) {
        float m = tf[wid*392 + j*32 + l];
        v[j].x *= m; v[j].y *= m;
    }
    __syncthreads();          // all PM reads done before tile reuse
    fft_dit(v, l, -1.f, stw);
#pragma unroll
    for (int k = 0; k < 12; k++) tile[wid*KST + l + 32*k] = v[k];
    __syncthreads();
#pragma unroll
    for (int i = 0; i < 12; i++) {
        int idx = threadIdx.x + i*256;
        int cc = idx & 7, hh = idx >> 3;
        base[hh*WD + sw0 + cc] = tile[cc*KST + hh];
    }
}

// K34: fused k3 (row IFFT + conj(coil) reduce, S in smem) + k4 (FISTA update).
// One block owns a row-pair (bb, h0, h0+1) across all 16 coils.
__global__ void __launch_bounds__(256) k34(const float* __restrict__ lam, float beta)
{
    LOAD_STW
    __shared__ float2 sred[8*384];     // per-warp partial sums
    int wid = threadIdx.x >> 5, l = threadIdx.x & 31;
    int bb = blockIdx.x / (HD/2);
    int h0 = (blockIdx.x % (HD/2)) * 2;
    __syncthreads();                   // stw visible

    // ---- Phase A: rows inverse FFT, conj(coil) accumulate (4 coils/warp)
    {
        int r = wid >> 2, q = wid & 3;
        int h = h0 + r;
        float2 acc[12];
#pragma unroll
        for (int k = 0; k < 12; k++) acc[k] = make_float2(0.f, 0.f);
        for (int cc = 0; cc < 4; cc++) {
            int c = q*4 + cc;
            const float2* row = g_T1 + ((bb*CD + c)*HD + h)*WD;
            float2 v[12];
#pragma unroll
            for (int j = 0; j < 12; j++) v[j] = row[j*32 + l];
            fft_dit(v, l, -1.f, stw);
            const float2* ch = g_csmc + (bb*CD + c)*HWD + h*WD;
#pragma unroll
            for (int k = 0; k < 12; k++) {
                int w = l + 32*k;
                float2 cv = ch[w];
                acc[k].x += cv.x*v[k].x + cv.y*v[k].y;   // conj(coil)*v
                acc[k].y += cv.x*v[k].y - cv.y*v[k].x;
            }
        }
#pragma unroll
        for (int k = 0; k < 12; k++) sred[wid*384 + k*32 + l] = acc[k];
    }
    __syncthreads();

    // ---- Phase B: reduce partials + FISTA update (all 256 threads, 3 px each)
    {
        const float sc = 1.0f/384.0f;
        float oml = 1.f - lam[0];
#pragma unroll
        for (int i = 0; i < 3; i++) {
            int p = threadIdx.x + i*256;       // 0..767
            int r = p / 384, w = p - r*384;
            float Sx = 0.f, Sy = 0.f;
#pragma unroll
            for (int q = 0; q < 4; q++) {
                float2 t = sred[(r*4+q)*384 + w];
                Sx += t.x; Sy += t.y;
            }
            Sx *= sc; Sy *= sc;
            int off = bb*HWD + (h0 + r)*WD + w;
            float2 yo = g_y[off], xo = g_x[off], Dv = g_D[off];
            float xr = fmaxf(oml*(yo.x - Sx) + Dv.x, 0.f);
            float xi = fmaxf(oml*(yo.y - Sy) + Dv.y, 0.f);
            g_x[off] = make_float2(xr, xi);
            g_y[off] = make_float2(xr + beta*(xr - xo.x), xi + beta*(xi - xo.y));
        }
    }
}

// final output: [B,2,H,W] float
__global__ void k5_out(float* __restrict__ out)
{
    int i = blockIdx.x*blockDim.x + threadIdx.x;
    if (i >= BD*HWD) return;
    int bb = i / HWD, r = i - bb*HWD;
    float2 v = g_x[i];
    out[(bb*2+0)*HWD + r] = v.x;
    out[(bb*2+1)*HWD + r] = v.y;
}

// ---------------- host ----------------
extern "C" void kernel_launch(void* const* d_in, const int* in_sizes, int n_in,
                              void* d_out, int out_size)
{
    const float* zk   = (const float*)d_in[0];   // z_k  [B,2,H,W]
    const float* x0   = (const float*)d_in[1];   // x0   [B,2,H,W]
    const float* csm  = (const float*)d_in[2];   // csm  [B,2,C,H,W]
    const float* lam  = (const float*)d_in[3];   // lam  [1]
    const int*   mask = (const int*)d_in[4];     // mask [B,H,W]
    float* out = (float*)d_out;

    // FISTA t-sequence (host, deterministic)
    float betas[NITER];
    double t = 1.0;
    for (int n = 0; n < NITER; n++) {
        double tn = (1.0 + sqrt(1.0 + 4.0*t*t)) / 2.0;
        betas[n] = (float)((t - 1.0) / tn);
        t = tn;
    }

    const int EW_BLOCKS = (BD*HWD) / 256;        // 2304
    init_tw_kernel<<<1, 384>>>();
    p1_sbar<<<EW_BLOCKS, 256>>>(csm);
    prep_csmc<<<(BD*CD*HWD)/256, 256>>>(csm);    // 36864
    pmask_kernel<<<EW_BLOCKS, 256>>>(mask);
    p2_rows<<<BD*HD/8, 256>>>(x0, mask);         // 192
    p3_cols<<<BD*(WD/8), 256>>>();               // 192
    kD_init<<<EW_BLOCKS, 256>>>(zk, lam);
    k1_rows<<<BD*CD*HD/8, 256>>>();              // 3072 — T1 for iteration 1

    for (int n = 1; n < NITER; n++) {
        k2_cols<<<BD*CD*(WD/8), 256>>>();        // 3072
        k34<<<BD*HD/2, 256>>>(lam, betas[n]);    // 768
        if (n < NITER-1)
            k1_rows<<<BD*CD*HD/8, 256>>>();      // feed next iteration
    }
    k5_out<<<EW_BLOCKS, 256>>>(out);
}